// round 3
// baseline (speedup 1.0000x reference)
#include <cuda_runtime.h>

#define DIM 80
#define DD 6400
#define D3 512000
#define NPTS 200000

// Scratch (device globals — no allocation in kernel_launch)
__device__ float g_f1[64 * D3];
__device__ float g_f2[64 * D3];
__device__ float g_wT1[32 * 27 * 64];   // [c][tap][o]
__device__ float g_wT2[64 * 27 * 64];

typedef unsigned long long u64;

__device__ __forceinline__ u64 pack2(float lo, float hi) {
    u64 r; asm("mov.b64 %0, {%1, %2};" : "=l"(r) : "f"(lo), "f"(hi)); return r;
}
__device__ __forceinline__ u64 bcast2(float v) { return pack2(v, v); }
__device__ __forceinline__ float2 unpack2(u64 p) {
    float2 f; asm("mov.b64 {%0, %1}, %2;" : "=f"(f.x), "=f"(f.y) : "l"(p)); return f;
}
__device__ __forceinline__ u64 fma2(u64 a, u64 b, u64 c) {
    u64 d; asm("fma.rn.f32x2 %0, %1, %2, %3;" : "=l"(d) : "l"(a), "l"(b), "l"(c));
    return d;
}

// ---------------------------------------------------------------------------
// One-time weight transpose: w[o][c][27] -> wT[c][tap][o]
// ---------------------------------------------------------------------------
template<int CIN>
__global__ void transpose_w_kernel(const float* __restrict__ w,
                                   float* __restrict__ wT)
{
    int idx = blockIdx.x * 256 + threadIdx.x;
    if (idx >= 64 * CIN * 27) return;
    int o = idx & 63;
    int r = idx >> 6;
    int tap = r % 27;
    int c = r / 27;
    wT[idx] = w[(o * CIN + c) * 27 + tap];
}

// ---------------------------------------------------------------------------
// 3D conv 3x3x3 pad 1 + bias + ReLU, FFMA2 packed over out-ch pairs.
// Block: 64 out-ch x (4z,4y,8x). Thread: 4 o x 8 x = 2 o-pairs x 8.
// Input rows padded to 12 floats (48B-aligned) -> float4 vector LDS.
// Weights read as ulonglong2 (LDS.128) whose halves feed fma2 directly.
// Input channels processed in chunks of 4 (smem 34.6KB -> high occupancy).
// ---------------------------------------------------------------------------
#define CHK 4
#define ROWW 12
#define CH_IN_FLTS (6 * 6 * ROWW)          // 432
#define SMEMC_FLTS (CHK * CH_IN_FLTS + CHK * 27 * 64)   // 1728 + 6912

template<int CIN, int STAGE>
__global__ __launch_bounds__(256) void conv3d_relu_kernel(
    const float* __restrict__ img,
    const float* __restrict__ bias)
{
    const float* in = (STAGE == 1) ? img : (const float*)g_f1;
    float* out      = (STAGE == 1) ? g_f1 : g_f2;
    const float* wT = (STAGE == 1) ? (const float*)g_wT1 : (const float*)g_wT2;

    extern __shared__ float sm[];
    float* in_s = sm;                      // [CHK][6][6][12]
    float* w_s  = sm + CHK * CH_IN_FLTS;   // [CHK][27][64]

    const int tid = threadIdx.x;
    const int x0 = blockIdx.x * 8;
    const int y0 = blockIdx.y * 4;
    const int z0 = blockIdx.z * 4;

    const int og = tid >> 4;    // 0..15
    const int sg = tid & 15;
    const int ob = og * 4;
    const int lz = sg >> 2;
    const int ly = sg & 3;

    u64 acc[2][8];
    #pragma unroll
    for (int ip = 0; ip < 2; ip++) {
        u64 b2 = pack2(bias[ob + 2 * ip], bias[ob + 2 * ip + 1]);
        #pragma unroll
        for (int j = 0; j < 8; j++) acc[ip][j] = b2;
    }

    for (int cb = 0; cb < CIN; cb += CHK) {
        __syncthreads();
        // stage CHK input channels (halo, zero pad, 12-wide rows)
        for (int i = tid; i < CHK * CH_IN_FLTS; i += 256) {
            int c  = i / CH_IN_FLTS;
            int r  = i - c * CH_IN_FLTS;
            int zz = r / (6 * ROWW);
            int r2 = r - zz * (6 * ROWW);
            int yy = r2 / ROWW;
            int xx = r2 - yy * ROWW;
            int gz = z0 + zz - 1, gy = y0 + yy - 1, gx = x0 + xx - 1;
            float v = 0.f;
            if (xx < 10 &&
                (unsigned)gz < (unsigned)DIM && (unsigned)gy < (unsigned)DIM &&
                (unsigned)gx < (unsigned)DIM)
                v = in[(cb + c) * D3 + gz * DD + gy * DIM + gx];
            in_s[i] = v;
        }
        // stage CHK channels of weights (coalesced float4 copy)
        {
            const float4* wsrc = (const float4*)(wT + cb * 27 * 64);
            float4* wdst = (float4*)w_s;
            for (int i = tid; i < CHK * 27 * 16; i += 256)
                wdst[i] = wsrc[i];
        }
        __syncthreads();

        #pragma unroll
        for (int c4 = 0; c4 < CHK; c4++) {
            const float* cin_s = in_s + c4 * CH_IN_FLTS;
            const float* wc    = w_s + c4 * 27 * 64 + ob;
            #pragma unroll
            for (int kz = 0; kz < 3; kz++) {
                #pragma unroll
                for (int ky = 0; ky < 3; ky++) {
                    const float* irow =
                        cin_s + ((lz + kz) * 6 + (ly + ky)) * ROWW;
                    float4 va = *(const float4*)irow;
                    float4 vb = *(const float4*)(irow + 4);
                    float2 vc = *(const float2*)(irow + 8);
                    u64 xb[10];
                    xb[0] = bcast2(va.x); xb[1] = bcast2(va.y);
                    xb[2] = bcast2(va.z); xb[3] = bcast2(va.w);
                    xb[4] = bcast2(vb.x); xb[5] = bcast2(vb.y);
                    xb[6] = bcast2(vb.z); xb[7] = bcast2(vb.w);
                    xb[8] = bcast2(vc.x); xb[9] = bcast2(vc.y);

                    const float* wrow = wc + (kz * 9 + ky * 3) * 64;
                    ulonglong2 wt0 = *(const ulonglong2*)(wrow);
                    ulonglong2 wt1 = *(const ulonglong2*)(wrow + 64);
                    ulonglong2 wt2 = *(const ulonglong2*)(wrow + 128);
                    #pragma unroll
                    for (int j = 0; j < 8; j++) {
                        acc[0][j] = fma2(wt0.x, xb[j],     acc[0][j]);
                        acc[0][j] = fma2(wt1.x, xb[j + 1], acc[0][j]);
                        acc[0][j] = fma2(wt2.x, xb[j + 2], acc[0][j]);
                        acc[1][j] = fma2(wt0.y, xb[j],     acc[1][j]);
                        acc[1][j] = fma2(wt1.y, xb[j + 1], acc[1][j]);
                        acc[1][j] = fma2(wt2.y, xb[j + 2], acc[1][j]);
                    }
                }
            }
        }
    }

    const int gz = z0 + lz, gy = y0 + ly;
    #pragma unroll
    for (int ip = 0; ip < 2; ip++) {
        float* r0 = out + (ob + 2 * ip) * D3 + gz * DD + gy * DIM + x0;
        float* r1 = r0 + D3;
        #pragma unroll
        for (int j = 0; j < 8; j++) {
            float2 v = unpack2(acc[ip][j]);
            r0[j] = fmaxf(v.x, 0.f);
            r1[j] = fmaxf(v.y, 0.f);
        }
    }
}

// ---------------------------------------------------------------------------
// Fused gather + 4-layer MLP, 512 threads, FFMA2 packed over point pairs.
// Shared (floats): X[64][64]@0  H1[256][64]@4096  H2[256][64]@20480
//                  Wb[256][33]@36864  vox[64]@45312
// ---------------------------------------------------------------------------
#define SM_X   0
#define SM_H1  4096
#define SM_H2  20480
#define SM_WB  36864
#define SM_VOX 45312
#define SM_MLP_FLOATS (45312 + 64)
#define MT 512

__device__ __forceinline__ void mlp_layer_w256(
    const float* __restrict__ in_s, int cin,
    const float* __restrict__ W, const float* __restrict__ bias,
    float* __restrict__ out_s, float* __restrict__ wbuf,
    bool relu, int tid)
{
    const int og = tid >> 2, pg = tid & 3;
    const int ob = og * 2, pb = pg * 16;

    u64 acc[2][8];
    #pragma unroll
    for (int i = 0; i < 2; i++) {
        u64 b2 = bcast2(bias[ob + i]);
        #pragma unroll
        for (int jj = 0; jj < 8; jj++) acc[i][jj] = b2;
    }

    for (int cb = 0; cb < cin; cb += 32) {
        __syncthreads();
        for (int i2 = tid; i2 < 256 * 32; i2 += MT) {
            int o = i2 >> 5, cc = i2 & 31;
            wbuf[o * 33 + cc] = W[o * cin + cb + cc];
        }
        __syncthreads();
        #pragma unroll 4
        for (int cc = 0; cc < 32; cc++) {
            const ulonglong2* xq =
                (const ulonglong2*)(in_s + (cb + cc) * 64 + pb);
            ulonglong2 q0 = xq[0], q1 = xq[1], q2 = xq[2], q3 = xq[3];
            #pragma unroll
            for (int i = 0; i < 2; i++) {
                u64 wv = bcast2(wbuf[(ob + i) * 33 + cc]);
                acc[i][0] = fma2(wv, q0.x, acc[i][0]);
                acc[i][1] = fma2(wv, q0.y, acc[i][1]);
                acc[i][2] = fma2(wv, q1.x, acc[i][2]);
                acc[i][3] = fma2(wv, q1.y, acc[i][3]);
                acc[i][4] = fma2(wv, q2.x, acc[i][4]);
                acc[i][5] = fma2(wv, q2.y, acc[i][5]);
                acc[i][6] = fma2(wv, q3.x, acc[i][6]);
                acc[i][7] = fma2(wv, q3.y, acc[i][7]);
            }
        }
    }
    __syncthreads();
    #pragma unroll
    for (int i = 0; i < 2; i++)
        #pragma unroll
        for (int jj = 0; jj < 8; jj++) {
            float2 v = unpack2(acc[i][jj]);
            if (relu) { v.x = fmaxf(v.x, 0.f); v.y = fmaxf(v.y, 0.f); }
            *(float2*)(out_s + (ob + i) * 64 + pb + 2 * jj) = v;
        }
    __syncthreads();
}

__device__ __forceinline__ void mlp_layer_w64(
    const float* __restrict__ in_s, int cin,
    const float* __restrict__ W, const float* __restrict__ bias,
    float* __restrict__ out_s, float* __restrict__ wbuf, int tid)
{
    const int o = tid & 63, pg = tid >> 6;
    const int pb = pg * 8;

    u64 acc[4];
    {
        u64 b2 = bcast2(bias[o]);
        #pragma unroll
        for (int jj = 0; jj < 4; jj++) acc[jj] = b2;
    }

    for (int cb = 0; cb < cin; cb += 32) {
        __syncthreads();
        for (int i2 = tid; i2 < 64 * 32; i2 += MT) {
            int oo = i2 >> 5, cc = i2 & 31;
            wbuf[oo * 33 + cc] = W[oo * cin + cb + cc];
        }
        __syncthreads();
        #pragma unroll 4
        for (int cc = 0; cc < 32; cc++) {
            const ulonglong2* xq =
                (const ulonglong2*)(in_s + (cb + cc) * 64 + pb);
            ulonglong2 q0 = xq[0], q1 = xq[1];
            u64 wv = bcast2(wbuf[o * 33 + cc]);
            acc[0] = fma2(wv, q0.x, acc[0]);
            acc[1] = fma2(wv, q0.y, acc[1]);
            acc[2] = fma2(wv, q1.x, acc[2]);
            acc[3] = fma2(wv, q1.y, acc[3]);
        }
    }
    __syncthreads();
    #pragma unroll
    for (int jj = 0; jj < 4; jj++) {
        float2 v = unpack2(acc[jj]);
        *(float2*)(out_s + o * 64 + pb + 2 * jj) = v;
    }
    __syncthreads();
}

__global__ __launch_bounds__(MT) void gather_mlp_kernel(
    const int* __restrict__ c0, const int* __restrict__ c1,
    const int* __restrict__ c2,
    const float* __restrict__ w1, const float* __restrict__ b1,
    const float* __restrict__ w2, const float* __restrict__ b2,
    const float* __restrict__ w3, const float* __restrict__ b3,
    const float* __restrict__ w4, const float* __restrict__ b4,
    float* __restrict__ out)
{
    extern __shared__ float sm[];
    float* X   = sm + SM_X;
    float* H1  = sm + SM_H1;
    float* H2  = sm + SM_H2;
    float* Wb  = sm + SM_WB;
    int*   vox = (int*)(sm + SM_VOX);

    const int tid = threadIdx.x;
    const int n0  = blockIdx.x * 64;

    if (tid < 64) {
        int n = n0 + tid;
        vox[tid] = c0[n] * DD + c1[n] * DIM + c2[n];
    }
    __syncthreads();

    const float* f2 = (const float*)g_f2;
    for (int i = tid; i < 64 * 64; i += MT) {
        int c = i >> 6, n = i & 63;
        X[i] = f2[c * D3 + vox[n]];
    }
    __syncthreads();

    mlp_layer_w256(X,  64,  w1, b1, H1, Wb, true, tid);
    mlp_layer_w256(H1, 256, w2, b2, H2, Wb, true, tid);
    mlp_layer_w64 (H2, 256, w3, b3, X,  Wb, tid);

    if (tid < 384) {
        int o = tid >> 6, n = tid & 63;
        float a = b4[o];
        #pragma unroll
        for (int c = 0; c < 64; c++)
            a = fmaf(w4[o * 64 + c], X[c * 64 + n], a);
        out[o * NPTS + n0 + n] = a;
    }
}

// ---------------------------------------------------------------------------
extern "C" void kernel_launch(void* const* d_in, const int* in_sizes, int n_in,
                              void* d_out, int out_size)
{
    const float* img = (const float*)d_in[0];
    const int*   c0  = (const int*)d_in[1];
    const int*   c1  = (const int*)d_in[2];
    const int*   c2  = (const int*)d_in[3];
    const float* we1 = (const float*)d_in[4];
    const float* be1 = (const float*)d_in[5];
    const float* we2 = (const float*)d_in[6];
    const float* be2 = (const float*)d_in[7];
    const float* wp1 = (const float*)d_in[8];
    const float* bp1 = (const float*)d_in[9];
    const float* wp2 = (const float*)d_in[10];
    const float* bp2 = (const float*)d_in[11];
    const float* wp3 = (const float*)d_in[12];
    const float* bp3 = (const float*)d_in[13];
    const float* wp4 = (const float*)d_in[14];
    const float* bp4 = (const float*)d_in[15];
    float* out = (float*)d_out;

    const int smemC = SMEMC_FLTS * 4;       // 34,560 B
    const int smemM = SM_MLP_FLOATS * 4;    // 181,504 B

    cudaFuncSetAttribute(conv3d_relu_kernel<32, 1>,
                         cudaFuncAttributeMaxDynamicSharedMemorySize, smemC);
    cudaFuncSetAttribute(conv3d_relu_kernel<64, 2>,
                         cudaFuncAttributeMaxDynamicSharedMemorySize, smemC);
    cudaFuncSetAttribute(gather_mlp_kernel,
                         cudaFuncAttributeMaxDynamicSharedMemorySize, smemM);

    float* wT1;  cudaGetSymbolAddress((void**)&wT1, g_wT1);
    float* wT2;  cudaGetSymbolAddress((void**)&wT2, g_wT2);

    transpose_w_kernel<32><<<(64 * 32 * 27 + 255) / 256, 256>>>(we1, wT1);
    transpose_w_kernel<64><<<(64 * 64 * 27 + 255) / 256, 256>>>(we2, wT2);

    dim3 cgrid(DIM / 8, DIM / 4, DIM / 4);   // (10, 20, 20)
    conv3d_relu_kernel<32, 1><<<cgrid, 256, smemC>>>(img, be1);
    conv3d_relu_kernel<64, 2><<<cgrid, 256, smemC>>>(img, be2);
    gather_mlp_kernel<<<NPTS / 64, MT, smemM>>>(c0, c1, c2,
                                                wp1, bp1, wp2, bp2,
                                                wp3, bp3, wp4, bp4, out);
}

// round 4
// speedup vs baseline: 1.3025x; 1.3025x over previous
#include <cuda_runtime.h>

#define DIM 80
#define DD 6400
#define D3 512000
#define NPTS 200000

// Scratch (device globals — no allocation in kernel_launch)
__device__ float g_f1[64 * D3];
__device__ float g_f2[64 * D3];
__device__ float g_wT1[32 * 27 * 64];   // [c][tap][o]
__device__ float g_wT2[64 * 27 * 64];

typedef unsigned long long u64;

__device__ __forceinline__ u64 pack2(float lo, float hi) {
    u64 r; asm("mov.b64 %0, {%1, %2};" : "=l"(r) : "f"(lo), "f"(hi)); return r;
}
__device__ __forceinline__ u64 bcast2(float v) { return pack2(v, v); }
__device__ __forceinline__ float2 unpack2(u64 p) {
    float2 f; asm("mov.b64 {%0, %1}, %2;" : "=f"(f.x), "=f"(f.y) : "l"(p)); return f;
}
__device__ __forceinline__ u64 fma2(u64 a, u64 b, u64 c) {
    u64 d; asm("fma.rn.f32x2 %0, %1, %2, %3;" : "=l"(d) : "l"(a), "l"(b), "l"(c));
    return d;
}

// ---------------------------------------------------------------------------
// One-time weight transpose: w[o][c][27] -> wT[c][tap][o]
// ---------------------------------------------------------------------------
template<int CIN>
__global__ void transpose_w_kernel(const float* __restrict__ w,
                                   float* __restrict__ wT)
{
    int idx = blockIdx.x * 256 + threadIdx.x;
    if (idx >= 64 * CIN * 27) return;
    int o = idx & 63;
    int r = idx >> 6;
    int tap = r % 27;
    int c = r / 27;
    wT[idx] = w[(o * CIN + c) * 27 + tap];
}

// ---------------------------------------------------------------------------
// 3D conv 3x3x3 pad 1 + bias + ReLU, FFMA2 packed over out-ch pairs.
// Block: 64 out-ch x (4z,4y,8x). Thread: 4 o x 8 x = 2 o-pairs x 8.
// Input rows padded to 12 floats -> float4/float2 vector LDS (3 per row).
// Weights read as ulonglong2 (LDS.128), halves feed fma2 directly.
// CHK=8 input channels per staging chunk (R2 sync count, R3 inner loop).
// ---------------------------------------------------------------------------
#define CHK 8
#define ROWW 12
#define CH_IN_FLTS (6 * 6 * ROWW)                       // 432
#define SMEMC_FLTS (CHK * CH_IN_FLTS + CHK * 27 * 64)   // 3456 + 13824

template<int CIN, int STAGE>
__global__ __launch_bounds__(256) void conv3d_relu_kernel(
    const float* __restrict__ img,
    const float* __restrict__ bias)
{
    const float* in = (STAGE == 1) ? img : (const float*)g_f1;
    float* out      = (STAGE == 1) ? g_f1 : g_f2;
    const float* wT = (STAGE == 1) ? (const float*)g_wT1 : (const float*)g_wT2;

    extern __shared__ float sm[];
    float* in_s = sm;                      // [CHK][6][6][12]
    float* w_s  = sm + CHK * CH_IN_FLTS;   // [CHK][27][64]

    const int tid = threadIdx.x;
    const int x0 = blockIdx.x * 8;
    const int y0 = blockIdx.y * 4;
    const int z0 = blockIdx.z * 4;

    const int og = tid >> 4;    // 0..15
    const int sg = tid & 15;
    const int ob = og * 4;
    const int lz = sg >> 2;
    const int ly = sg & 3;

    u64 acc[2][8];
    #pragma unroll
    for (int ip = 0; ip < 2; ip++) {
        u64 b2 = pack2(bias[ob + 2 * ip], bias[ob + 2 * ip + 1]);
        #pragma unroll
        for (int j = 0; j < 8; j++) acc[ip][j] = b2;
    }

    for (int cb = 0; cb < CIN; cb += CHK) {
        __syncthreads();
        // stage CHK input channels (halo, zero pad, 12-wide rows)
        for (int i = tid; i < CHK * CH_IN_FLTS; i += 256) {
            int c  = i / CH_IN_FLTS;
            int r  = i - c * CH_IN_FLTS;
            int zz = r / (6 * ROWW);
            int r2 = r - zz * (6 * ROWW);
            int yy = r2 / ROWW;
            int xx = r2 - yy * ROWW;
            int gz = z0 + zz - 1, gy = y0 + yy - 1, gx = x0 + xx - 1;
            float v = 0.f;
            if (xx < 10 &&
                (unsigned)gz < (unsigned)DIM && (unsigned)gy < (unsigned)DIM &&
                (unsigned)gx < (unsigned)DIM)
                v = in[(cb + c) * D3 + gz * DD + gy * DIM + gx];
            in_s[i] = v;
        }
        // stage CHK channels of weights (coalesced float4 copy)
        {
            const float4* wsrc = (const float4*)(wT + cb * 27 * 64);
            float4* wdst = (float4*)w_s;
            for (int i = tid; i < CHK * 27 * 16; i += 256)
                wdst[i] = wsrc[i];
        }
        __syncthreads();

        #pragma unroll
        for (int c8 = 0; c8 < CHK; c8++) {
            const float* cin_s = in_s + c8 * CH_IN_FLTS;
            const float* wc    = w_s + c8 * 27 * 64 + ob;
            #pragma unroll
            for (int kz = 0; kz < 3; kz++) {
                #pragma unroll
                for (int ky = 0; ky < 3; ky++) {
                    const float* irow =
                        cin_s + ((lz + kz) * 6 + (ly + ky)) * ROWW;
                    float4 va = *(const float4*)irow;
                    float4 vb = *(const float4*)(irow + 4);
                    float2 vc = *(const float2*)(irow + 8);
                    u64 xb[10];
                    xb[0] = bcast2(va.x); xb[1] = bcast2(va.y);
                    xb[2] = bcast2(va.z); xb[3] = bcast2(va.w);
                    xb[4] = bcast2(vb.x); xb[5] = bcast2(vb.y);
                    xb[6] = bcast2(vb.z); xb[7] = bcast2(vb.w);
                    xb[8] = bcast2(vc.x); xb[9] = bcast2(vc.y);

                    const float* wrow = wc + (kz * 9 + ky * 3) * 64;
                    ulonglong2 wt0 = *(const ulonglong2*)(wrow);
                    ulonglong2 wt1 = *(const ulonglong2*)(wrow + 64);
                    ulonglong2 wt2 = *(const ulonglong2*)(wrow + 128);
                    #pragma unroll
                    for (int j = 0; j < 8; j++) {
                        acc[0][j] = fma2(wt0.x, xb[j],     acc[0][j]);
                        acc[0][j] = fma2(wt1.x, xb[j + 1], acc[0][j]);
                        acc[0][j] = fma2(wt2.x, xb[j + 2], acc[0][j]);
                        acc[1][j] = fma2(wt0.y, xb[j],     acc[1][j]);
                        acc[1][j] = fma2(wt1.y, xb[j + 1], acc[1][j]);
                        acc[1][j] = fma2(wt2.y, xb[j + 2], acc[1][j]);
                    }
                }
            }
        }
    }

    const int gz = z0 + lz, gy = y0 + ly;
    #pragma unroll
    for (int ip = 0; ip < 2; ip++) {
        float* r0 = out + (ob + 2 * ip) * D3 + gz * DD + gy * DIM + x0;
        float* r1 = r0 + D3;
        #pragma unroll
        for (int j = 0; j < 8; j++) {
            float2 v = unpack2(acc[ip][j]);
            r0[j] = fmaxf(v.x, 0.f);
            r1[j] = fmaxf(v.y, 0.f);
        }
    }
}

// ---------------------------------------------------------------------------
// Fused gather + 4-layer MLP. 32 points/block, 256 threads.
// smem 107.6KB -> 2 CTAs/SM for barrier-latency overlap.
// Shared (floats): X[64][32]@0  H1[256][32]@2048  H2[256][32]@10240
//                  Wb[256][33]@18432  vox[32]@26880
// ---------------------------------------------------------------------------
#define PTS 32
#define SM_X   0
#define SM_H1  2048
#define SM_H2  10240
#define SM_WB  18432
#define SM_VOX 26880
#define SM_MLP_FLOATS (26880 + 32)
#define MT 256

// 256-wide layer: thread = 2 out x 16 pts (8 point-pairs)
__device__ __forceinline__ void mlp_layer_w256(
    const float* __restrict__ in_s, int cin,
    const float* __restrict__ W, const float* __restrict__ bias,
    float* __restrict__ out_s, float* __restrict__ wbuf,
    bool relu, int tid)
{
    const int og = tid >> 1, pg = tid & 1;
    const int ob = og * 2, pb = pg * 16;

    u64 acc[2][8];
    #pragma unroll
    for (int i = 0; i < 2; i++) {
        u64 b2 = bcast2(bias[ob + i]);
        #pragma unroll
        for (int jj = 0; jj < 8; jj++) acc[i][jj] = b2;
    }

    for (int cb = 0; cb < cin; cb += 32) {
        __syncthreads();
        for (int i2 = tid; i2 < 256 * 32; i2 += MT) {
            int o = i2 >> 5, cc = i2 & 31;
            wbuf[o * 33 + cc] = W[o * cin + cb + cc];
        }
        __syncthreads();
        #pragma unroll 4
        for (int cc = 0; cc < 32; cc++) {
            const ulonglong2* xq =
                (const ulonglong2*)(in_s + (cb + cc) * PTS + pb);
            ulonglong2 q0 = xq[0], q1 = xq[1], q2 = xq[2], q3 = xq[3];
            #pragma unroll
            for (int i = 0; i < 2; i++) {
                u64 wv = bcast2(wbuf[(ob + i) * 33 + cc]);
                acc[i][0] = fma2(wv, q0.x, acc[i][0]);
                acc[i][1] = fma2(wv, q0.y, acc[i][1]);
                acc[i][2] = fma2(wv, q1.x, acc[i][2]);
                acc[i][3] = fma2(wv, q1.y, acc[i][3]);
                acc[i][4] = fma2(wv, q2.x, acc[i][4]);
                acc[i][5] = fma2(wv, q2.y, acc[i][5]);
                acc[i][6] = fma2(wv, q3.x, acc[i][6]);
                acc[i][7] = fma2(wv, q3.y, acc[i][7]);
            }
        }
    }
    __syncthreads();
    #pragma unroll
    for (int i = 0; i < 2; i++)
        #pragma unroll
        for (int jj = 0; jj < 8; jj++) {
            float2 v = unpack2(acc[i][jj]);
            if (relu) { v.x = fmaxf(v.x, 0.f); v.y = fmaxf(v.y, 0.f); }
            *(float2*)(out_s + (ob + i) * PTS + pb + 2 * jj) = v;
        }
    __syncthreads();
}

// 64-wide layer (no relu): thread = 1 out x 8 pts (4 point-pairs)
__device__ __forceinline__ void mlp_layer_w64(
    const float* __restrict__ in_s, int cin,
    const float* __restrict__ W, const float* __restrict__ bias,
    float* __restrict__ out_s, float* __restrict__ wbuf, int tid)
{
    const int o = tid & 63, pg = tid >> 6;   // pg 0..3
    const int pb = pg * 8;

    u64 acc[4];
    {
        u64 b2 = bcast2(bias[o]);
        #pragma unroll
        for (int jj = 0; jj < 4; jj++) acc[jj] = b2;
    }

    for (int cb = 0; cb < cin; cb += 32) {
        __syncthreads();
        for (int i2 = tid; i2 < 64 * 32; i2 += MT) {
            int oo = i2 >> 5, cc = i2 & 31;
            wbuf[oo * 33 + cc] = W[oo * cin + cb + cc];
        }
        __syncthreads();
        #pragma unroll 4
        for (int cc = 0; cc < 32; cc++) {
            const ulonglong2* xq =
                (const ulonglong2*)(in_s + (cb + cc) * PTS + pb);
            ulonglong2 q0 = xq[0], q1 = xq[1];
            u64 wv = bcast2(wbuf[o * 33 + cc]);
            acc[0] = fma2(wv, q0.x, acc[0]);
            acc[1] = fma2(wv, q0.y, acc[1]);
            acc[2] = fma2(wv, q1.x, acc[2]);
            acc[3] = fma2(wv, q1.y, acc[3]);
        }
    }
    __syncthreads();
    #pragma unroll
    for (int jj = 0; jj < 4; jj++) {
        float2 v = unpack2(acc[jj]);
        *(float2*)(out_s + o * PTS + pb + 2 * jj) = v;
    }
    __syncthreads();
}

__global__ __launch_bounds__(MT) void gather_mlp_kernel(
    const int* __restrict__ c0, const int* __restrict__ c1,
    const int* __restrict__ c2,
    const float* __restrict__ w1, const float* __restrict__ b1,
    const float* __restrict__ w2, const float* __restrict__ b2,
    const float* __restrict__ w3, const float* __restrict__ b3,
    const float* __restrict__ w4, const float* __restrict__ b4,
    float* __restrict__ out)
{
    extern __shared__ float sm[];
    float* X   = sm + SM_X;
    float* H1  = sm + SM_H1;
    float* H2  = sm + SM_H2;
    float* Wb  = sm + SM_WB;
    int*   vox = (int*)(sm + SM_VOX);

    const int tid = threadIdx.x;
    const int n0  = blockIdx.x * PTS;

    if (tid < PTS) {
        int n = n0 + tid;
        vox[tid] = c0[n] * DD + c1[n] * DIM + c2[n];
    }
    __syncthreads();

    const float* f2 = (const float*)g_f2;
    for (int i = tid; i < 64 * PTS; i += MT) {
        int c = i >> 5, n = i & 31;
        X[i] = f2[c * D3 + vox[n]];
    }
    __syncthreads();

    mlp_layer_w256(X,  64,  w1, b1, H1, Wb, true, tid);
    mlp_layer_w256(H1, 256, w2, b2, H2, Wb, true, tid);
    mlp_layer_w64 (H2, 256, w3, b3, X,  Wb, tid);

    if (tid < 6 * PTS) {
        int o = tid >> 5, n = tid & 31;
        float a = b4[o];
        #pragma unroll
        for (int c = 0; c < 64; c++)
            a = fmaf(w4[o * 64 + c], X[c * PTS + n], a);
        out[o * NPTS + n0 + n] = a;
    }
}

// ---------------------------------------------------------------------------
extern "C" void kernel_launch(void* const* d_in, const int* in_sizes, int n_in,
                              void* d_out, int out_size)
{
    const float* img = (const float*)d_in[0];
    const int*   c0  = (const int*)d_in[1];
    const int*   c1  = (const int*)d_in[2];
    const int*   c2  = (const int*)d_in[3];
    const float* we1 = (const float*)d_in[4];
    const float* be1 = (const float*)d_in[5];
    const float* we2 = (const float*)d_in[6];
    const float* be2 = (const float*)d_in[7];
    const float* wp1 = (const float*)d_in[8];
    const float* bp1 = (const float*)d_in[9];
    const float* wp2 = (const float*)d_in[10];
    const float* bp2 = (const float*)d_in[11];
    const float* wp3 = (const float*)d_in[12];
    const float* bp3 = (const float*)d_in[13];
    const float* wp4 = (const float*)d_in[14];
    const float* bp4 = (const float*)d_in[15];
    float* out = (float*)d_out;

    const int smemC = SMEMC_FLTS * 4;       // 69,120 B
    const int smemM = SM_MLP_FLOATS * 4;    // 107,648 B

    cudaFuncSetAttribute(conv3d_relu_kernel<32, 1>,
                         cudaFuncAttributeMaxDynamicSharedMemorySize, smemC);
    cudaFuncSetAttribute(conv3d_relu_kernel<64, 2>,
                         cudaFuncAttributeMaxDynamicSharedMemorySize, smemC);
    cudaFuncSetAttribute(gather_mlp_kernel,
                         cudaFuncAttributeMaxDynamicSharedMemorySize, smemM);

    float* wT1;  cudaGetSymbolAddress((void**)&wT1, g_wT1);
    float* wT2;  cudaGetSymbolAddress((void**)&wT2, g_wT2);

    transpose_w_kernel<32><<<(64 * 32 * 27 + 255) / 256, 256>>>(we1, wT1);
    transpose_w_kernel<64><<<(64 * 64 * 27 + 255) / 256, 256>>>(we2, wT2);

    dim3 cgrid(DIM / 8, DIM / 4, DIM / 4);   // (10, 20, 20)
    conv3d_relu_kernel<32, 1><<<cgrid, 256, smemC>>>(img, be1);
    conv3d_relu_kernel<64, 2><<<cgrid, 256, smemC>>>(img, be2);
    gather_mlp_kernel<<<NPTS / PTS, MT, smemM>>>(c0, c1, c2,
                                                 wp1, bp1, wp2, bp2,
                                                 wp3, bp3, wp4, bp4, out);
}

// round 5
// speedup vs baseline: 1.3317x; 1.0224x over previous
#include <cuda_runtime.h>

#define DIM 80
#define DD 6400
#define D3 512000
#define NPTS 200000

// Scratch (device globals — no allocation in kernel_launch)
__device__ float g_f1[64 * D3];
__device__ float g_f2[64 * D3];
__device__ float g_wT1[32 * 27 * 64];   // [c][tap][o]
__device__ float g_wT2[64 * 27 * 64];

typedef unsigned long long u64;

__device__ __forceinline__ u64 pack2(float lo, float hi) {
    u64 r; asm("mov.b64 %0, {%1, %2};" : "=l"(r) : "f"(lo), "f"(hi)); return r;
}
__device__ __forceinline__ u64 bcast2(float v) { return pack2(v, v); }
__device__ __forceinline__ float2 unpack2(u64 p) {
    float2 f; asm("mov.b64 {%0, %1}, %2;" : "=f"(f.x), "=f"(f.y) : "l"(p)); return f;
}
__device__ __forceinline__ u64 fma2(u64 a, u64 b, u64 c) {
    u64 d; asm("fma.rn.f32x2 %0, %1, %2, %3;" : "=l"(d) : "l"(a), "l"(b), "l"(c));
    return d;
}

// ---------------------------------------------------------------------------
// One-time weight transpose: w[o][c][27] -> wT[c][tap][o]
// ---------------------------------------------------------------------------
template<int CIN>
__global__ void transpose_w_kernel(const float* __restrict__ w,
                                   float* __restrict__ wT)
{
    int idx = blockIdx.x * 256 + threadIdx.x;
    if (idx >= 64 * CIN * 27) return;
    int o = idx & 63;
    int r = idx >> 6;
    int tap = r % 27;
    int c = r / 27;
    wT[idx] = w[(o * CIN + c) * 27 + tap];
}

// ---------------------------------------------------------------------------
// 3D conv 3x3x3 pad 1 + bias + ReLU, FFMA2 over out-ch pairs.
// Block tile: 64 oc x (z4, y8, x8). 256 threads.
// Thread tile: 4 oc x 2 y x 8 x (sliding window over 4 input rows / kz).
// Lane map: lane = og_lo(2b) | lyh(1b) | lz(2b)  -> warp = 4 oc-grp x 8 rows
//   => row loads ~1 wavefront, weight LDS.128 (4 oc) ~1 wavefront.
// ---------------------------------------------------------------------------
#define CHK 8
#define ZH 6
#define YHALO 10
#define ROWW 12
#define CH_FLTS (ZH * YHALO * ROWW)                     // 720
#define SMEMC_FLTS (CHK * CH_FLTS + CHK * 27 * 64)      // 5760 + 13824

template<int CIN, int STAGE>
__global__ __launch_bounds__(256, 2) void conv3d_relu_kernel(
    const float* __restrict__ img,
    const float* __restrict__ bias)
{
    const float* in = (STAGE == 1) ? img : (const float*)g_f1;
    float* out      = (STAGE == 1) ? g_f1 : g_f2;
    const float* wT = (STAGE == 1) ? (const float*)g_wT1 : (const float*)g_wT2;

    extern __shared__ float sm[];
    float* in_s = sm;                     // [CHK][6][10][12]
    float* w_s  = sm + CHK * CH_FLTS;     // [CHK][27][64]

    const int tid = threadIdx.x;
    const int x0 = blockIdx.x * 8;
    const int y0 = blockIdx.y * 8;
    const int z0 = blockIdx.z * 4;

    const int lane = tid & 31;
    const int warp = tid >> 5;
    const int og_lo = lane & 3;
    const int lyh   = (lane >> 2) & 1;
    const int lz    = lane >> 3;          // 0..3
    const int og_hi = warp & 3;
    const int yh    = warp >> 2;          // 0..1
    const int ob    = (og_hi * 4 + og_lo) * 4;   // 4 out-channels
    const int ybase = yh * 4 + lyh * 2;          // 0,2,4,6

    u64 acc[2][2][8];   // [oc-pair][dy][x]
    #pragma unroll
    for (int p = 0; p < 2; p++) {
        u64 b2 = pack2(bias[ob + 2 * p], bias[ob + 2 * p + 1]);
        #pragma unroll
        for (int dy = 0; dy < 2; dy++)
            #pragma unroll
            for (int j = 0; j < 8; j++) acc[p][dy][j] = b2;
    }

    for (int cb = 0; cb < CIN; cb += CHK) {
        __syncthreads();
        // stage CHK input channels (halo, zero pad, 12-wide rows)
        for (int i = tid; i < CHK * CH_FLTS; i += 256) {
            int c  = i / CH_FLTS;
            int r  = i - c * CH_FLTS;
            int zz = r / (YHALO * ROWW);
            int r2 = r - zz * (YHALO * ROWW);
            int yy = r2 / ROWW;
            int xx = r2 - yy * ROWW;
            int gz = z0 + zz - 1, gy = y0 + yy - 1, gx = x0 + xx - 1;
            float v = 0.f;
            if (xx < 10 &&
                (unsigned)gz < (unsigned)DIM && (unsigned)gy < (unsigned)DIM &&
                (unsigned)gx < (unsigned)DIM)
                v = in[(cb + c) * D3 + gz * DD + gy * DIM + gx];
            in_s[i] = v;
        }
        // stage CHK channels of weights (coalesced float4 copy)
        {
            const float4* wsrc = (const float4*)(wT + cb * 27 * 64);
            float4* wdst = (float4*)w_s;
            for (int i = tid; i < CHK * 27 * 16; i += 256)
                wdst[i] = wsrc[i];
        }
        __syncthreads();

        #pragma unroll
        for (int c8 = 0; c8 < CHK; c8++) {
            const float* cin_s = in_s + c8 * CH_FLTS;
            const float* wbase = w_s + c8 * 27 * 64 + ob;
            #pragma unroll
            for (int kz = 0; kz < 3; kz++) {
                const float* zplane = cin_s + (lz + kz) * (YHALO * ROWW);
                #pragma unroll
                for (int yy = 0; yy < 4; yy++) {
                    const float* irow = zplane + (ybase + yy) * ROWW;
                    float4 va = *(const float4*)irow;
                    float4 vb = *(const float4*)(irow + 4);
                    float2 vc = *(const float2*)(irow + 8);
                    u64 xb[10];
                    xb[0] = bcast2(va.x); xb[1] = bcast2(va.y);
                    xb[2] = bcast2(va.z); xb[3] = bcast2(va.w);
                    xb[4] = bcast2(vb.x); xb[5] = bcast2(vb.y);
                    xb[6] = bcast2(vb.z); xb[7] = bcast2(vb.w);
                    xb[8] = bcast2(vc.x); xb[9] = bcast2(vc.y);

                    #pragma unroll
                    for (int dy = 0; dy < 2; dy++) {
                        const int ky = yy - dy;
                        if (ky >= 0 && ky <= 2) {
                            #pragma unroll
                            for (int kx = 0; kx < 3; kx++) {
                                ulonglong2 w2 = *(const ulonglong2*)
                                    (wbase + ((kz * 3 + ky) * 3 + kx) * 64);
                                #pragma unroll
                                for (int j = 0; j < 8; j++) {
                                    acc[0][dy][j] =
                                        fma2(w2.x, xb[j + kx], acc[0][dy][j]);
                                    acc[1][dy][j] =
                                        fma2(w2.y, xb[j + kx], acc[1][dy][j]);
                                }
                            }
                        }
                    }
                }
            }
        }
    }

    const int gz = z0 + lz;
    #pragma unroll
    for (int p = 0; p < 2; p++) {
        #pragma unroll
        for (int dy = 0; dy < 2; dy++) {
            const int gy = y0 + ybase + dy;
            float f0[8], f1[8];
            #pragma unroll
            for (int j = 0; j < 8; j++) {
                float2 v = unpack2(acc[p][dy][j]);
                f0[j] = fmaxf(v.x, 0.f);
                f1[j] = fmaxf(v.y, 0.f);
            }
            float* r0 = out + (ob + 2 * p) * D3 + gz * DD + gy * DIM + x0;
            float* r1 = r0 + D3;
            *(float4*)(r0)     = make_float4(f0[0], f0[1], f0[2], f0[3]);
            *(float4*)(r0 + 4) = make_float4(f0[4], f0[5], f0[6], f0[7]);
            *(float4*)(r1)     = make_float4(f1[0], f1[1], f1[2], f1[3]);
            *(float4*)(r1 + 4) = make_float4(f1[4], f1[5], f1[6], f1[7]);
        }
    }
}

// ---------------------------------------------------------------------------
// Fused gather + 4-layer MLP. 32 points/block, 256 threads, 2 CTAs/SM.
// Shared (floats): X[64][32]@0  H1[256][32]@2048  H2[256][32]@10240
//                  Wb[256][33]@18432  vox[32]@26880
// ---------------------------------------------------------------------------
#define PTS 32
#define SM_X   0
#define SM_H1  2048
#define SM_H2  10240
#define SM_WB  18432
#define SM_VOX 26880
#define SM_MLP_FLOATS (26880 + 32)
#define MT 256

__device__ __forceinline__ void mlp_layer_w256(
    const float* __restrict__ in_s, int cin,
    const float* __restrict__ W, const float* __restrict__ bias,
    float* __restrict__ out_s, float* __restrict__ wbuf,
    bool relu, int tid)
{
    const int og = tid >> 1, pg = tid & 1;
    const int ob = og * 2, pb = pg * 16;

    u64 acc[2][8];
    #pragma unroll
    for (int i = 0; i < 2; i++) {
        u64 b2 = bcast2(bias[ob + i]);
        #pragma unroll
        for (int jj = 0; jj < 8; jj++) acc[i][jj] = b2;
    }

    for (int cb = 0; cb < cin; cb += 32) {
        __syncthreads();
        for (int i2 = tid; i2 < 256 * 32; i2 += MT) {
            int o = i2 >> 5, cc = i2 & 31;
            wbuf[o * 33 + cc] = W[o * cin + cb + cc];
        }
        __syncthreads();
        #pragma unroll 4
        for (int cc = 0; cc < 32; cc++) {
            const ulonglong2* xq =
                (const ulonglong2*)(in_s + (cb + cc) * PTS + pb);
            ulonglong2 q0 = xq[0], q1 = xq[1], q2 = xq[2], q3 = xq[3];
            #pragma unroll
            for (int i = 0; i < 2; i++) {
                u64 wv = bcast2(wbuf[(ob + i) * 33 + cc]);
                acc[i][0] = fma2(wv, q0.x, acc[i][0]);
                acc[i][1] = fma2(wv, q0.y, acc[i][1]);
                acc[i][2] = fma2(wv, q1.x, acc[i][2]);
                acc[i][3] = fma2(wv, q1.y, acc[i][3]);
                acc[i][4] = fma2(wv, q2.x, acc[i][4]);
                acc[i][5] = fma2(wv, q2.y, acc[i][5]);
                acc[i][6] = fma2(wv, q3.x, acc[i][6]);
                acc[i][7] = fma2(wv, q3.y, acc[i][7]);
            }
        }
    }
    __syncthreads();
    #pragma unroll
    for (int i = 0; i < 2; i++)
        #pragma unroll
        for (int jj = 0; jj < 8; jj++) {
            float2 v = unpack2(acc[i][jj]);
            if (relu) { v.x = fmaxf(v.x, 0.f); v.y = fmaxf(v.y, 0.f); }
            *(float2*)(out_s + (ob + i) * PTS + pb + 2 * jj) = v;
        }
    __syncthreads();
}

__device__ __forceinline__ void mlp_layer_w64(
    const float* __restrict__ in_s, int cin,
    const float* __restrict__ W, const float* __restrict__ bias,
    float* __restrict__ out_s, float* __restrict__ wbuf, int tid)
{
    const int o = tid & 63, pg = tid >> 6;   // pg 0..3
    const int pb = pg * 8;

    u64 acc[4];
    {
        u64 b2 = bcast2(bias[o]);
        #pragma unroll
        for (int jj = 0; jj < 4; jj++) acc[jj] = b2;
    }

    for (int cb = 0; cb < cin; cb += 32) {
        __syncthreads();
        for (int i2 = tid; i2 < 64 * 32; i2 += MT) {
            int oo = i2 >> 5, cc = i2 & 31;
            wbuf[oo * 33 + cc] = W[oo * cin + cb + cc];
        }
        __syncthreads();
        #pragma unroll 4
        for (int cc = 0; cc < 32; cc++) {
            const ulonglong2* xq =
                (const ulonglong2*)(in_s + (cb + cc) * PTS + pb);
            ulonglong2 q0 = xq[0], q1 = xq[1];
            u64 wv = bcast2(wbuf[o * 33 + cc]);
            acc[0] = fma2(wv, q0.x, acc[0]);
            acc[1] = fma2(wv, q0.y, acc[1]);
            acc[2] = fma2(wv, q1.x, acc[2]);
            acc[3] = fma2(wv, q1.y, acc[3]);
        }
    }
    __syncthreads();
    #pragma unroll
    for (int jj = 0; jj < 4; jj++) {
        float2 v = unpack2(acc[jj]);
        *(float2*)(out_s + o * PTS + pb + 2 * jj) = v;
    }
    __syncthreads();
}

__global__ __launch_bounds__(MT) void gather_mlp_kernel(
    const int* __restrict__ c0, const int* __restrict__ c1,
    const int* __restrict__ c2,
    const float* __restrict__ w1, const float* __restrict__ b1,
    const float* __restrict__ w2, const float* __restrict__ b2,
    const float* __restrict__ w3, const float* __restrict__ b3,
    const float* __restrict__ w4, const float* __restrict__ b4,
    float* __restrict__ out)
{
    extern __shared__ float sm[];
    float* X   = sm + SM_X;
    float* H1  = sm + SM_H1;
    float* H2  = sm + SM_H2;
    float* Wb  = sm + SM_WB;
    int*   vox = (int*)(sm + SM_VOX);

    const int tid = threadIdx.x;
    const int n0  = blockIdx.x * PTS;

    if (tid < PTS) {
        int n = n0 + tid;
        vox[tid] = c0[n] * DD + c1[n] * DIM + c2[n];
    }
    __syncthreads();

    const float* f2 = (const float*)g_f2;
    for (int i = tid; i < 64 * PTS; i += MT) {
        int c = i >> 5, n = i & 31;
        X[i] = f2[c * D3 + vox[n]];
    }
    __syncthreads();

    mlp_layer_w256(X,  64,  w1, b1, H1, Wb, true, tid);
    mlp_layer_w256(H1, 256, w2, b2, H2, Wb, true, tid);
    mlp_layer_w64 (H2, 256, w3, b3, X,  Wb, tid);

    if (tid < 6 * PTS) {
        int o = tid >> 5, n = tid & 31;
        float a = b4[o];
        #pragma unroll
        for (int c = 0; c < 64; c++)
            a = fmaf(w4[o * 64 + c], X[c * PTS + n], a);
        out[o * NPTS + n0 + n] = a;
    }
}

// ---------------------------------------------------------------------------
extern "C" void kernel_launch(void* const* d_in, const int* in_sizes, int n_in,
                              void* d_out, int out_size)
{
    const float* img = (const float*)d_in[0];
    const int*   c0  = (const int*)d_in[1];
    const int*   c1  = (const int*)d_in[2];
    const int*   c2  = (const int*)d_in[3];
    const float* we1 = (const float*)d_in[4];
    const float* be1 = (const float*)d_in[5];
    const float* we2 = (const float*)d_in[6];
    const float* be2 = (const float*)d_in[7];
    const float* wp1 = (const float*)d_in[8];
    const float* bp1 = (const float*)d_in[9];
    const float* wp2 = (const float*)d_in[10];
    const float* bp2 = (const float*)d_in[11];
    const float* wp3 = (const float*)d_in[12];
    const float* bp3 = (const float*)d_in[13];
    const float* wp4 = (const float*)d_in[14];
    const float* bp4 = (const float*)d_in[15];
    float* out = (float*)d_out;

    const int smemC = SMEMC_FLTS * 4;       // 78,336 B
    const int smemM = SM_MLP_FLOATS * 4;    // 107,648 B

    cudaFuncSetAttribute(conv3d_relu_kernel<32, 1>,
                         cudaFuncAttributeMaxDynamicSharedMemorySize, smemC);
    cudaFuncSetAttribute(conv3d_relu_kernel<64, 2>,
                         cudaFuncAttributeMaxDynamicSharedMemorySize, smemC);
    cudaFuncSetAttribute(gather_mlp_kernel,
                         cudaFuncAttributeMaxDynamicSharedMemorySize, smemM);

    float* wT1;  cudaGetSymbolAddress((void**)&wT1, g_wT1);
    float* wT2;  cudaGetSymbolAddress((void**)&wT2, g_wT2);

    transpose_w_kernel<32><<<(64 * 32 * 27 + 255) / 256, 256>>>(we1, wT1);
    transpose_w_kernel<64><<<(64 * 64 * 27 + 255) / 256, 256>>>(we2, wT2);

    dim3 cgrid(DIM / 8, DIM / 8, DIM / 4);   // (10, 10, 20)
    conv3d_relu_kernel<32, 1><<<cgrid, 256, smemC>>>(img, be1);
    conv3d_relu_kernel<64, 2><<<cgrid, 256, smemC>>>(img, be2);
    gather_mlp_kernel<<<NPTS / PTS, MT, smemM>>>(c0, c1, c2,
                                                 wp1, bp1, wp2, bp2,
                                                 wp3, bp3, wp4, bp4, out);
}

// round 7
// speedup vs baseline: 1.8925x; 1.4211x over previous
#include <cuda_runtime.h>
#include <cuda_bf16.h>
#include <cstdint>

#define DIM 80
#define DD 6400
#define D3 512000
#define NPTS 200000

typedef unsigned long long u64;
typedef unsigned int u32;

// ---------------------------------------------------------------------------
// Device scratch (no allocations in kernel_launch)
// ---------------------------------------------------------------------------
__device__ __nv_bfloat16 g_xhi[D3 * 32];   // img [pixel][32ch] bf16 hi
__device__ __nv_bfloat16 g_xlo[D3 * 32];   // lo residual
__device__ __nv_bfloat16 g_f1hi[D3 * 64];  // conv1 out [pixel][64ch]
__device__ __nv_bfloat16 g_f1lo[D3 * 64];
__device__ float         g_f2[D3 * 64];    // conv2 out [pixel][64ch] fp32
__device__ __nv_bfloat16 g_w1hi[14 * 64 * 64], g_w1lo[14 * 64 * 64]; // [chunk][oc][64k]
__device__ __nv_bfloat16 g_w2hi[27 * 64 * 64], g_w2lo[27 * 64 * 64];

__device__ __forceinline__ u32 pkbf(__nv_bfloat16 a, __nv_bfloat16 b) {
    return (u32)__bfloat16_as_ushort(a) | ((u32)__bfloat16_as_ushort(b) << 16);
}

__device__ __forceinline__ void mma16816(float* d, const u32* a, const u32* b) {
    asm volatile(
        "mma.sync.aligned.m16n8k16.row.col.f32.bf16.bf16.f32 "
        "{%0,%1,%2,%3}, {%4,%5,%6,%7}, {%8,%9}, {%0,%1,%2,%3};"
        : "+f"(d[0]), "+f"(d[1]), "+f"(d[2]), "+f"(d[3])
        : "r"(a[0]), "r"(a[1]), "r"(a[2]), "r"(a[3]), "r"(b[0]), "r"(b[1]));
}

// ---------------------------------------------------------------------------
// Prep: transpose img -> [pixel][32ch] bf16 hi/lo
// ---------------------------------------------------------------------------
__global__ void prep_img(const float* __restrict__ img) {
    int p = blockIdx.x * 256 + threadIdx.x;
    u32 hw[16], lw[16];
    #pragma unroll
    for (int c = 0; c < 32; c += 2) {
        float a = img[c * D3 + p];
        float b = img[(c + 1) * D3 + p];
        __nv_bfloat16 ah = __float2bfloat16_rn(a);
        __nv_bfloat16 al = __float2bfloat16_rn(a - __bfloat162float(ah));
        __nv_bfloat16 bh = __float2bfloat16_rn(b);
        __nv_bfloat16 bl = __float2bfloat16_rn(b - __bfloat162float(bh));
        hw[c >> 1] = pkbf(ah, bh);
        lw[c >> 1] = pkbf(al, bl);
    }
    uint4* oh = (uint4*)(g_xhi + (size_t)p * 32);
    uint4* ol = (uint4*)(g_xlo + (size_t)p * 32);
    #pragma unroll
    for (int q = 0; q < 4; q++) {
        oh[q] = make_uint4(hw[q*4], hw[q*4+1], hw[q*4+2], hw[q*4+3]);
        ol[q] = make_uint4(lw[q*4], lw[q*4+1], lw[q*4+2], lw[q*4+3]);
    }
}

// conv1 weights: [14 chunks][64 oc][64 k] with k = t*32 + c, tap = 2*chunk + t
__global__ void prep_w1(const float* __restrict__ w) {
    int idx = blockIdx.x * 256 + threadIdx.x;
    if (idx >= 14 * 4096) return;
    int j = idx >> 12, r = idx & 4095, o = r >> 6, k = r & 63;
    int t = k >> 5, c = k & 31, tp = 2 * j + t;
    float v = (tp <= 26) ? w[(o * 32 + c) * 27 + tp] : 0.f;
    __nv_bfloat16 h = __float2bfloat16_rn(v);
    g_w1hi[idx] = h;
    g_w1lo[idx] = __float2bfloat16_rn(v - __bfloat162float(h));
}
// conv2 weights: [27 taps][64 oc][64 c]
__global__ void prep_w2(const float* __restrict__ w) {
    int idx = blockIdx.x * 256 + threadIdx.x;
    if (idx >= 27 * 4096) return;
    int j = idx >> 12, r = idx & 4095, o = r >> 6, c = r & 63;
    float v = w[(o * 64 + c) * 27 + j];
    __nv_bfloat16 h = __float2bfloat16_rn(v);
    g_w2hi[idx] = h;
    g_w2lo[idx] = __float2bfloat16_rn(v - __bfloat162float(h));
}

// ---------------------------------------------------------------------------
// Conv via mma.sync (HMMA): D[128px][64oc] += A[128px][64k] * W[64oc][64k]^T
// per tap-chunk; bf16 hi/lo, 3 products (hh + hl + lh), fp32 accum in regs.
// Smem rows strided 144B: fragment LDS bank = (4g + tg) -> conflict-free.
// Warps 4x2, warp tile 32x32 = 2 m16 x 4 n8 mma tiles.
// ---------------------------------------------------------------------------
#define RSTR 144
#define SA_HI 0
#define SA_LO (128 * RSTR)
#define SW_HI (2 * 128 * RSTR)
#define SW_LO (2 * 128 * RSTR + 64 * RSTR)
#define SMEM_CONV (2 * 128 * RSTR + 2 * 64 * RSTR)   // 55296

template<int STAGE>
__global__ __launch_bounds__(256) void conv_mma(const float* __restrict__ bias)
{
    constexpr int NCH = (STAGE == 1) ? 14 : 27;
    const __nv_bfloat16* Xhi = (STAGE == 1) ? g_xhi : g_f1hi;
    const __nv_bfloat16* Xlo = (STAGE == 1) ? g_xlo : g_f1lo;
    const __nv_bfloat16* Whi = (STAGE == 1) ? g_w1hi : g_w2hi;
    const __nv_bfloat16* Wlo = (STAGE == 1) ? g_w1lo : g_w2lo;

    extern __shared__ char smem[];
    const int tid = threadIdx.x;
    const int warp = tid >> 5, lane = tid & 31;
    const int p0 = blockIdx.x * 128;

    // staging role: thread stages 64B (hi & lo) of row m
    const int m = tid >> 1, half = tid & 1;
    const int p = p0 + m;
    const int z = p / DD;
    const int rr = p - z * DD;
    const int y = rr / DIM;
    const int x = rr - y * DIM;

    // mma role
    const int wm = warp >> 1, wn = warp & 1;
    const int g = lane >> 2, tg = lane & 3;

    float acc[2][4][4];
    #pragma unroll
    for (int mt = 0; mt < 2; mt++)
        #pragma unroll
        for (int nt = 0; nt < 4; nt++)
            #pragma unroll
            for (int q = 0; q < 4; q++) acc[mt][nt][q] = 0.f;

    for (int j = 0; j < NCH; j++) {
        __syncthreads();
        // ---- stage A (128 rows x 64 bf16 hi + lo), masked for padding ----
        {
            int kz, ky, kx;
            bool tapok = true;
            if (STAGE == 1) {
                int tp = 2 * j + half;
                if (tp > 26) tapok = false;
                kz = tp / 9; ky = (tp / 3) % 3; kx = tp % 3;
            } else {
                kz = j / 9; ky = (j / 3) % 3; kx = j % 3;
            }
            bool v = tapok &&
                     (unsigned)(z + kz - 1) < 80u &&
                     (unsigned)(y + ky - 1) < 80u &&
                     (unsigned)(x + kx - 1) < 80u;
            int ps = p + (kz - 1) * DD + (ky - 1) * DIM + (kx - 1);
            const int CE = (STAGE == 1) ? 32 : 64;
            const uint4* shi = (const uint4*)(Xhi + (size_t)ps * CE) +
                               ((STAGE == 1) ? 0 : half * 4);
            const uint4* slo = (const uint4*)(Xlo + (size_t)ps * CE) +
                               ((STAGE == 1) ? 0 : half * 4);
            const uint4 zero = make_uint4(0, 0, 0, 0);
            #pragma unroll
            for (int i = 0; i < 4; i++) {
                u32 off = m * RSTR + half * 64 + i * 16;
                *(uint4*)(smem + SA_HI + off) = v ? shi[i] : zero;
                *(uint4*)(smem + SA_LO + off) = v ? slo[i] : zero;
            }
        }
        // ---- stage W (64 rows x 64 bf16 hi + lo) ----
        {
            const uint4* wh = (const uint4*)(Whi + j * 4096);
            const uint4* wl = (const uint4*)(Wlo + j * 4096);
            #pragma unroll
            for (int u = tid; u < 512; u += 256) {
                u32 off = (u >> 3) * RSTR + (u & 7) * 16;
                *(uint4*)(smem + SW_HI + off) = wh[u];
                *(uint4*)(smem + SW_LO + off) = wl[u];
            }
        }
        __syncthreads();

        // ---- compute: 4 k16 steps ----
        #pragma unroll
        for (int ks = 0; ks < 4; ks++) {
            u32 ah[2][4], al[2][4];
            #pragma unroll
            for (int mt = 0; mt < 2; mt++) {
                u32 base = (wm * 32 + mt * 16 + g) * RSTR + ks * 32 + tg * 4;
                ah[mt][0] = *(const u32*)(smem + SA_HI + base);
                ah[mt][1] = *(const u32*)(smem + SA_HI + base + 8 * RSTR);
                ah[mt][2] = *(const u32*)(smem + SA_HI + base + 16);
                ah[mt][3] = *(const u32*)(smem + SA_HI + base + 8 * RSTR + 16);
                al[mt][0] = *(const u32*)(smem + SA_LO + base);
                al[mt][1] = *(const u32*)(smem + SA_LO + base + 8 * RSTR);
                al[mt][2] = *(const u32*)(smem + SA_LO + base + 16);
                al[mt][3] = *(const u32*)(smem + SA_LO + base + 8 * RSTR + 16);
            }
            u32 bh[4][2], bl[4][2];
            #pragma unroll
            for (int nt = 0; nt < 4; nt++) {
                u32 base = (wn * 32 + nt * 8 + g) * RSTR + ks * 32 + tg * 4;
                bh[nt][0] = *(const u32*)(smem + SW_HI + base);
                bh[nt][1] = *(const u32*)(smem + SW_HI + base + 16);
                bl[nt][0] = *(const u32*)(smem + SW_LO + base);
                bl[nt][1] = *(const u32*)(smem + SW_LO + base + 16);
            }
            #pragma unroll
            for (int mt = 0; mt < 2; mt++)
                #pragma unroll
                for (int nt = 0; nt < 4; nt++) {
                    mma16816(acc[mt][nt], ah[mt], bh[nt]);
                    mma16816(acc[mt][nt], ah[mt], bl[nt]);
                    mma16816(acc[mt][nt], al[mt], bh[nt]);
                }
        }
    }

    // ---- epilogue: bias + ReLU ----
    #pragma unroll
    for (int mt = 0; mt < 2; mt++) {
        #pragma unroll
        for (int nt = 0; nt < 4; nt++) {
            const int n = wn * 32 + nt * 8 + tg * 2;
            const float b0 = __ldg(bias + n), b1 = __ldg(bias + n + 1);
            const int pixA = p0 + wm * 32 + mt * 16 + g;
            const int pixB = pixA + 8;
            float v0 = fmaxf(acc[mt][nt][0] + b0, 0.f);
            float v1 = fmaxf(acc[mt][nt][1] + b1, 0.f);
            float v2 = fmaxf(acc[mt][nt][2] + b0, 0.f);
            float v3 = fmaxf(acc[mt][nt][3] + b1, 0.f);
            if (STAGE == 1) {
                __nv_bfloat16 h0 = __float2bfloat16_rn(v0);
                __nv_bfloat16 h1 = __float2bfloat16_rn(v1);
                __nv_bfloat16 h2 = __float2bfloat16_rn(v2);
                __nv_bfloat16 h3 = __float2bfloat16_rn(v3);
                *(u32*)(g_f1hi + (size_t)pixA * 64 + n) = pkbf(h0, h1);
                *(u32*)(g_f1hi + (size_t)pixB * 64 + n) = pkbf(h2, h3);
                *(u32*)(g_f1lo + (size_t)pixA * 64 + n) =
                    pkbf(__float2bfloat16_rn(v0 - __bfloat162float(h0)),
                         __float2bfloat16_rn(v1 - __bfloat162float(h1)));
                *(u32*)(g_f1lo + (size_t)pixB * 64 + n) =
                    pkbf(__float2bfloat16_rn(v2 - __bfloat162float(h2)),
                         __float2bfloat16_rn(v3 - __bfloat162float(h3)));
            } else {
                *(float2*)(g_f2 + (size_t)pixA * 64 + n) = make_float2(v0, v1);
                *(float2*)(g_f2 + (size_t)pixB * 64 + n) = make_float2(v2, v3);
            }
        }
    }
}

// ---------------------------------------------------------------------------
// Fused gather + 4-layer MLP (FFMA2 over point pairs) — unchanged from R5/R6
// ---------------------------------------------------------------------------
__device__ __forceinline__ u64 pack2(float lo, float hi) {
    u64 r; asm("mov.b64 %0, {%1, %2};" : "=l"(r) : "f"(lo), "f"(hi)); return r;
}
__device__ __forceinline__ u64 bcast2(float v) { return pack2(v, v); }
__device__ __forceinline__ float2 unpack2(u64 p) {
    float2 f; asm("mov.b64 {%0, %1}, %2;" : "=f"(f.x), "=f"(f.y) : "l"(p)); return f;
}
__device__ __forceinline__ u64 fma2(u64 a, u64 b, u64 c) {
    u64 d; asm("fma.rn.f32x2 %0, %1, %2, %3;" : "=l"(d) : "l"(a), "l"(b), "l"(c));
    return d;
}

#define PTS 32
#define SM_X   0
#define SM_H1  2048
#define SM_H2  10240
#define SM_WB  18432
#define SM_VOX 26880
#define SM_MLP_FLOATS (26880 + 32)
#define MT 256

__device__ __forceinline__ void mlp_layer_w256(
    const float* __restrict__ in_s, int cin,
    const float* __restrict__ W, const float* __restrict__ bias,
    float* __restrict__ out_s, float* __restrict__ wbuf,
    bool relu, int tid)
{
    const int og = tid >> 1, pg = tid & 1;
    const int ob = og * 2, pb = pg * 16;

    u64 acc[2][8];
    #pragma unroll
    for (int i = 0; i < 2; i++) {
        u64 b2 = bcast2(bias[ob + i]);
        #pragma unroll
        for (int jj = 0; jj < 8; jj++) acc[i][jj] = b2;
    }

    for (int cb = 0; cb < cin; cb += 32) {
        __syncthreads();
        for (int i2 = tid; i2 < 256 * 32; i2 += MT) {
            int o = i2 >> 5, cc = i2 & 31;
            wbuf[o * 33 + cc] = W[o * cin + cb + cc];
        }
        __syncthreads();
        #pragma unroll 4
        for (int cc = 0; cc < 32; cc++) {
            const ulonglong2* xq =
                (const ulonglong2*)(in_s + (cb + cc) * PTS + pb);
            ulonglong2 q0 = xq[0], q1 = xq[1], q2 = xq[2], q3 = xq[3];
            #pragma unroll
            for (int i = 0; i < 2; i++) {
                u64 wv = bcast2(wbuf[(ob + i) * 33 + cc]);
                acc[i][0] = fma2(wv, q0.x, acc[i][0]);
                acc[i][1] = fma2(wv, q0.y, acc[i][1]);
                acc[i][2] = fma2(wv, q1.x, acc[i][2]);
                acc[i][3] = fma2(wv, q1.y, acc[i][3]);
                acc[i][4] = fma2(wv, q2.x, acc[i][4]);
                acc[i][5] = fma2(wv, q2.y, acc[i][5]);
                acc[i][6] = fma2(wv, q3.x, acc[i][6]);
                acc[i][7] = fma2(wv, q3.y, acc[i][7]);
            }
        }
    }
    __syncthreads();
    #pragma unroll
    for (int i = 0; i < 2; i++)
        #pragma unroll
        for (int jj = 0; jj < 8; jj++) {
            float2 v = unpack2(acc[i][jj]);
            if (relu) { v.x = fmaxf(v.x, 0.f); v.y = fmaxf(v.y, 0.f); }
            *(float2*)(out_s + (ob + i) * PTS + pb + 2 * jj) = v;
        }
    __syncthreads();
}

__device__ __forceinline__ void mlp_layer_w64(
    const float* __restrict__ in_s, int cin,
    const float* __restrict__ W, const float* __restrict__ bias,
    float* __restrict__ out_s, float* __restrict__ wbuf, int tid)
{
    const int o = tid & 63, pg = tid >> 6;
    const int pb = pg * 8;

    u64 acc[4];
    {
        u64 b2 = bcast2(bias[o]);
        #pragma unroll
        for (int jj = 0; jj < 4; jj++) acc[jj] = b2;
    }

    for (int cb = 0; cb < cin; cb += 32) {
        __syncthreads();
        for (int i2 = tid; i2 < 64 * 32; i2 += MT) {
            int oo = i2 >> 5, cc = i2 & 31;
            wbuf[oo * 33 + cc] = W[oo * cin + cb + cc];
        }
        __syncthreads();
        #pragma unroll 4
        for (int cc = 0; cc < 32; cc++) {
            const ulonglong2* xq =
                (const ulonglong2*)(in_s + (cb + cc) * PTS + pb);
            ulonglong2 q0 = xq[0], q1 = xq[1];
            u64 wv = bcast2(wbuf[o * 33 + cc]);
            acc[0] = fma2(wv, q0.x, acc[0]);
            acc[1] = fma2(wv, q0.y, acc[1]);
            acc[2] = fma2(wv, q1.x, acc[2]);
            acc[3] = fma2(wv, q1.y, acc[3]);
        }
    }
    __syncthreads();
    #pragma unroll
    for (int jj = 0; jj < 4; jj++) {
        float2 v = unpack2(acc[jj]);
        *(float2*)(out_s + o * PTS + pb + 2 * jj) = v;
    }
    __syncthreads();
}

__global__ __launch_bounds__(MT) void gather_mlp_kernel(
    const int* __restrict__ c0, const int* __restrict__ c1,
    const int* __restrict__ c2,
    const float* __restrict__ w1, const float* __restrict__ b1,
    const float* __restrict__ w2, const float* __restrict__ b2,
    const float* __restrict__ w3, const float* __restrict__ b3,
    const float* __restrict__ w4, const float* __restrict__ b4,
    float* __restrict__ out)
{
    extern __shared__ float sm[];
    float* X   = sm + SM_X;
    float* H1  = sm + SM_H1;
    float* H2  = sm + SM_H2;
    float* Wb  = sm + SM_WB;
    int*   vox = (int*)(sm + SM_VOX);

    const int tid = threadIdx.x;
    const int n0  = blockIdx.x * PTS;

    if (tid < PTS) {
        int n = n0 + tid;
        vox[tid] = c0[n] * DD + c1[n] * DIM + c2[n];
    }
    __syncthreads();

    // gather from pixel-major f2: point n's channels are contiguous
    for (int it = tid; it < PTS * 16; it += MT) {
        int n = it >> 4, q = it & 15;
        float4 v = *(const float4*)(g_f2 + (size_t)vox[n] * 64 + q * 4);
        X[(q * 4 + 0) * PTS + n] = v.x;
        X[(q * 4 + 1) * PTS + n] = v.y;
        X[(q * 4 + 2) * PTS + n] = v.z;
        X[(q * 4 + 3) * PTS + n] = v.w;
    }
    __syncthreads();

    mlp_layer_w256(X,  64,  w1, b1, H1, Wb, true, tid);
    mlp_layer_w256(H1, 256, w2, b2, H2, Wb, true, tid);
    mlp_layer_w64 (H2, 256, w3, b3, X,  Wb, tid);

    if (tid < 6 * PTS) {
        int o = tid >> 5, n = tid & 31;
        float a = b4[o];
        #pragma unroll
        for (int c = 0; c < 64; c++)
            a = fmaf(w4[o * 64 + c], X[c * PTS + n], a);
        out[o * NPTS + n0 + n] = a;
    }
}

// ---------------------------------------------------------------------------
extern "C" void kernel_launch(void* const* d_in, const int* in_sizes, int n_in,
                              void* d_out, int out_size)
{
    const float* img = (const float*)d_in[0];
    const int*   c0  = (const int*)d_in[1];
    const int*   c1  = (const int*)d_in[2];
    const int*   c2  = (const int*)d_in[3];
    const float* we1 = (const float*)d_in[4];
    const float* be1 = (const float*)d_in[5];
    const float* we2 = (const float*)d_in[6];
    const float* be2 = (const float*)d_in[7];
    const float* wp1 = (const float*)d_in[8];
    const float* bp1 = (const float*)d_in[9];
    const float* wp2 = (const float*)d_in[10];
    const float* bp2 = (const float*)d_in[11];
    const float* wp3 = (const float*)d_in[12];
    const float* bp3 = (const float*)d_in[13];
    const float* wp4 = (const float*)d_in[14];
    const float* bp4 = (const float*)d_in[15];
    float* out = (float*)d_out;

    const int smemM = SM_MLP_FLOATS * 4;

    cudaFuncSetAttribute(conv_mma<1>,
                         cudaFuncAttributeMaxDynamicSharedMemorySize, SMEM_CONV);
    cudaFuncSetAttribute(conv_mma<2>,
                         cudaFuncAttributeMaxDynamicSharedMemorySize, SMEM_CONV);
    cudaFuncSetAttribute(gather_mlp_kernel,
                         cudaFuncAttributeMaxDynamicSharedMemorySize, smemM);

    prep_img<<<2000, 256>>>(img);
    prep_w1<<<(14 * 4096 + 255) / 256, 256>>>(we1);
    prep_w2<<<(27 * 4096 + 255) / 256, 256>>>(we2);

    conv_mma<1><<<4000, 256, SMEM_CONV>>>(be1);
    conv_mma<2><<<4000, 256, SMEM_CONV>>>(be2);

    gather_mlp_kernel<<<NPTS / PTS, MT, smemM>>>(c0, c1, c2,
                                                 wp1, bp1, wp2, bp2,
                                                 wp3, bp3, wp4, bp4, out);
}

// round 9
// speedup vs baseline: 2.4353x; 1.2868x over previous
#include <cuda_runtime.h>
#include <cuda_bf16.h>
#include <cstdint>

#define DIM 80
#define DD 6400
#define D3 512000
#define NPTS 200000
#define NPAD 200064   // 1563 * 128

typedef unsigned long long u64;
typedef unsigned int u32;

// ---------------------------------------------------------------------------
// Device scratch (no allocations in kernel_launch)
// ---------------------------------------------------------------------------
__device__ __nv_bfloat16 g_xhi[D3 * 32];
__device__ __nv_bfloat16 g_xlo[D3 * 32];
__device__ __nv_bfloat16 g_f1hi[D3 * 64];
__device__ __nv_bfloat16 g_f1lo[D3 * 64];
__device__ float         g_f2[D3 * 64];
__device__ __nv_bfloat16 g_w1hi[14 * 64 * 64], g_w1lo[14 * 64 * 64];
__device__ __nv_bfloat16 g_w2hi[27 * 64 * 64], g_w2lo[27 * 64 * 64];
// MLP
__device__ __nv_bfloat16 g_h1hi[(size_t)NPAD * 256], g_h1lo[(size_t)NPAD * 256];
__device__ __nv_bfloat16 g_h2hi[(size_t)NPAD * 256], g_h2lo[(size_t)NPAD * 256];
__device__ float         g_h3[(size_t)NPAD * 64];
__device__ __nv_bfloat16 g_mw1hi[256 * 64],  g_mw1lo[256 * 64];
__device__ __nv_bfloat16 g_mw2hi[256 * 256], g_mw2lo[256 * 256];
__device__ __nv_bfloat16 g_mw3hi[64 * 256],  g_mw3lo[64 * 256];

__device__ __forceinline__ u32 pkbf(__nv_bfloat16 a, __nv_bfloat16 b) {
    return (u32)__bfloat16_as_ushort(a) | ((u32)__bfloat16_as_ushort(b) << 16);
}

__device__ __forceinline__ void mma16816(float* d, const u32* a, const u32* b) {
    asm volatile(
        "mma.sync.aligned.m16n8k16.row.col.f32.bf16.bf16.f32 "
        "{%0,%1,%2,%3}, {%4,%5,%6,%7}, {%8,%9}, {%0,%1,%2,%3};"
        : "+f"(d[0]), "+f"(d[1]), "+f"(d[2]), "+f"(d[3])
        : "r"(a[0]), "r"(a[1]), "r"(a[2]), "r"(a[3]), "r"(b[0]), "r"(b[1]));
}

// ---------------------------------------------------------------------------
// Prep kernels
// ---------------------------------------------------------------------------
__global__ void prep_img(const float* __restrict__ img) {
    int p = blockIdx.x * 256 + threadIdx.x;
    u32 hw[16], lw[16];
    #pragma unroll
    for (int c = 0; c < 32; c += 2) {
        float a = img[c * D3 + p];
        float b = img[(c + 1) * D3 + p];
        __nv_bfloat16 ah = __float2bfloat16_rn(a);
        __nv_bfloat16 al = __float2bfloat16_rn(a - __bfloat162float(ah));
        __nv_bfloat16 bh = __float2bfloat16_rn(b);
        __nv_bfloat16 bl = __float2bfloat16_rn(b - __bfloat162float(bh));
        hw[c >> 1] = pkbf(ah, bh);
        lw[c >> 1] = pkbf(al, bl);
    }
    uint4* oh = (uint4*)(g_xhi + (size_t)p * 32);
    uint4* ol = (uint4*)(g_xlo + (size_t)p * 32);
    #pragma unroll
    for (int q = 0; q < 4; q++) {
        oh[q] = make_uint4(hw[q*4], hw[q*4+1], hw[q*4+2], hw[q*4+3]);
        ol[q] = make_uint4(lw[q*4], lw[q*4+1], lw[q*4+2], lw[q*4+3]);
    }
}

__global__ void prep_w1(const float* __restrict__ w) {
    int idx = blockIdx.x * 256 + threadIdx.x;
    if (idx >= 14 * 4096) return;
    int j = idx >> 12, r = idx & 4095, o = r >> 6, k = r & 63;
    int t = k >> 5, c = k & 31, tp = 2 * j + t;
    float v = (tp <= 26) ? w[(o * 32 + c) * 27 + tp] : 0.f;
    __nv_bfloat16 h = __float2bfloat16_rn(v);
    g_w1hi[idx] = h;
    g_w1lo[idx] = __float2bfloat16_rn(v - __bfloat162float(h));
}
__global__ void prep_w2(const float* __restrict__ w) {
    int idx = blockIdx.x * 256 + threadIdx.x;
    if (idx >= 27 * 4096) return;
    int j = idx >> 12, r = idx & 4095, o = r >> 6, c = r & 63;
    float v = w[(o * 64 + c) * 27 + j];
    __nv_bfloat16 h = __float2bfloat16_rn(v);
    g_w2hi[idx] = h;
    g_w2lo[idx] = __float2bfloat16_rn(v - __bfloat162float(h));
}

__global__ void prep_wmlp(const float* __restrict__ src,
                          __nv_bfloat16* __restrict__ dhi,
                          __nv_bfloat16* __restrict__ dlo, int n) {
    int i = blockIdx.x * 256 + threadIdx.x;
    if (i >= n) return;
    float v = src[i];
    __nv_bfloat16 h = __float2bfloat16_rn(v);
    dhi[i] = h;
    dlo[i] = __float2bfloat16_rn(v - __bfloat162float(h));
}

// ---------------------------------------------------------------------------
// Conv via mma.sync — unchanged from R7 (proven)
// ---------------------------------------------------------------------------
#define RSTR 144
#define SA_HI 0
#define SA_LO (128 * RSTR)
#define SW_HI (2 * 128 * RSTR)
#define SW_LO (2 * 128 * RSTR + 64 * RSTR)
#define SMEM_CONV (2 * 128 * RSTR + 2 * 64 * RSTR)

template<int STAGE>
__global__ __launch_bounds__(256) void conv_mma(const float* __restrict__ bias)
{
    constexpr int NCH = (STAGE == 1) ? 14 : 27;
    const __nv_bfloat16* Xhi = (STAGE == 1) ? g_xhi : g_f1hi;
    const __nv_bfloat16* Xlo = (STAGE == 1) ? g_xlo : g_f1lo;
    const __nv_bfloat16* Whi = (STAGE == 1) ? g_w1hi : g_w2hi;
    const __nv_bfloat16* Wlo = (STAGE == 1) ? g_w1lo : g_w2lo;

    extern __shared__ char smem[];
    const int tid = threadIdx.x;
    const int warp = tid >> 5, lane = tid & 31;
    const int p0 = blockIdx.x * 128;

    const int m = tid >> 1, half = tid & 1;
    const int p = p0 + m;
    const int z = p / DD;
    const int rr = p - z * DD;
    const int y = rr / DIM;
    const int x = rr - y * DIM;

    const int wm = warp >> 1, wn = warp & 1;
    const int g = lane >> 2, tg = lane & 3;

    float acc[2][4][4];
    #pragma unroll
    for (int mt = 0; mt < 2; mt++)
        #pragma unroll
        for (int nt = 0; nt < 4; nt++)
            #pragma unroll
            for (int q = 0; q < 4; q++) acc[mt][nt][q] = 0.f;

    for (int j = 0; j < NCH; j++) {
        __syncthreads();
        {
            int kz, ky, kx;
            bool tapok = true;
            if (STAGE == 1) {
                int tp = 2 * j + half;
                if (tp > 26) tapok = false;
                kz = tp / 9; ky = (tp / 3) % 3; kx = tp % 3;
            } else {
                kz = j / 9; ky = (j / 3) % 3; kx = j % 3;
            }
            bool v = tapok &&
                     (unsigned)(z + kz - 1) < 80u &&
                     (unsigned)(y + ky - 1) < 80u &&
                     (unsigned)(x + kx - 1) < 80u;
            int ps = p + (kz - 1) * DD + (ky - 1) * DIM + (kx - 1);
            const int CE = (STAGE == 1) ? 32 : 64;
            const uint4* shi = (const uint4*)(Xhi + (size_t)ps * CE) +
                               ((STAGE == 1) ? 0 : half * 4);
            const uint4* slo = (const uint4*)(Xlo + (size_t)ps * CE) +
                               ((STAGE == 1) ? 0 : half * 4);
            const uint4 zero = make_uint4(0, 0, 0, 0);
            #pragma unroll
            for (int i = 0; i < 4; i++) {
                u32 off = m * RSTR + half * 64 + i * 16;
                *(uint4*)(smem + SA_HI + off) = v ? shi[i] : zero;
                *(uint4*)(smem + SA_LO + off) = v ? slo[i] : zero;
            }
        }
        {
            const uint4* wh = (const uint4*)(Whi + j * 4096);
            const uint4* wl = (const uint4*)(Wlo + j * 4096);
            #pragma unroll
            for (int u = tid; u < 512; u += 256) {
                u32 off = (u >> 3) * RSTR + (u & 7) * 16;
                *(uint4*)(smem + SW_HI + off) = wh[u];
                *(uint4*)(smem + SW_LO + off) = wl[u];
            }
        }
        __syncthreads();

        #pragma unroll
        for (int ks = 0; ks < 4; ks++) {
            u32 ah[2][4], al[2][4];
            #pragma unroll
            for (int mt = 0; mt < 2; mt++) {
                u32 base = (wm * 32 + mt * 16 + g) * RSTR + ks * 32 + tg * 4;
                ah[mt][0] = *(const u32*)(smem + SA_HI + base);
                ah[mt][1] = *(const u32*)(smem + SA_HI + base + 8 * RSTR);
                ah[mt][2] = *(const u32*)(smem + SA_HI + base + 16);
                ah[mt][3] = *(const u32*)(smem + SA_HI + base + 8 * RSTR + 16);
                al[mt][0] = *(const u32*)(smem + SA_LO + base);
                al[mt][1] = *(const u32*)(smem + SA_LO + base + 8 * RSTR);
                al[mt][2] = *(const u32*)(smem + SA_LO + base + 16);
                al[mt][3] = *(const u32*)(smem + SA_LO + base + 8 * RSTR + 16);
            }
            u32 bh[4][2], bl[4][2];
            #pragma unroll
            for (int nt = 0; nt < 4; nt++) {
                u32 base = (wn * 32 + nt * 8 + g) * RSTR + ks * 32 + tg * 4;
                bh[nt][0] = *(const u32*)(smem + SW_HI + base);
                bh[nt][1] = *(const u32*)(smem + SW_HI + base + 16);
                bl[nt][0] = *(const u32*)(smem + SW_LO + base);
                bl[nt][1] = *(const u32*)(smem + SW_LO + base + 16);
            }
            #pragma unroll
            for (int mt = 0; mt < 2; mt++)
                #pragma unroll
                for (int nt = 0; nt < 4; nt++) {
                    mma16816(acc[mt][nt], ah[mt], bh[nt]);
                    mma16816(acc[mt][nt], ah[mt], bl[nt]);
                    mma16816(acc[mt][nt], al[mt], bh[nt]);
                }
        }
    }

    #pragma unroll
    for (int mt = 0; mt < 2; mt++) {
        #pragma unroll
        for (int nt = 0; nt < 4; nt++) {
            const int n = wn * 32 + nt * 8 + tg * 2;
            const float b0 = __ldg(bias + n), b1 = __ldg(bias + n + 1);
            const int pixA = p0 + wm * 32 + mt * 16 + g;
            const int pixB = pixA + 8;
            float v0 = fmaxf(acc[mt][nt][0] + b0, 0.f);
            float v1 = fmaxf(acc[mt][nt][1] + b1, 0.f);
            float v2 = fmaxf(acc[mt][nt][2] + b0, 0.f);
            float v3 = fmaxf(acc[mt][nt][3] + b1, 0.f);
            if (STAGE == 1) {
                __nv_bfloat16 h0 = __float2bfloat16_rn(v0);
                __nv_bfloat16 h1 = __float2bfloat16_rn(v1);
                __nv_bfloat16 h2 = __float2bfloat16_rn(v2);
                __nv_bfloat16 h3 = __float2bfloat16_rn(v3);
                *(u32*)(g_f1hi + (size_t)pixA * 64 + n) = pkbf(h0, h1);
                *(u32*)(g_f1hi + (size_t)pixB * 64 + n) = pkbf(h2, h3);
                *(u32*)(g_f1lo + (size_t)pixA * 64 + n) =
                    pkbf(__float2bfloat16_rn(v0 - __bfloat162float(h0)),
                         __float2bfloat16_rn(v1 - __bfloat162float(h1)));
                *(u32*)(g_f1lo + (size_t)pixB * 64 + n) =
                    pkbf(__float2bfloat16_rn(v2 - __bfloat162float(h2)),
                         __float2bfloat16_rn(v3 - __bfloat162float(h3)));
            } else {
                *(float2*)(g_f2 + (size_t)pixA * 64 + n) = make_float2(v0, v1);
                *(float2*)(g_f2 + (size_t)pixB * 64 + n) = make_float2(v2, v3);
            }
        }
    }
}

// ---------------------------------------------------------------------------
// MLP GEMM via mma.sync.
// MODE 1: gather(g_f2)->bf16, 64->256, relu, out g_h1 (hi/lo)
// MODE 2: g_h1, 256->256, relu, out g_h2 (hi/lo)
// MODE 3: g_h2, 256->64, no relu, out g_h3 (fp32)
// CTA: 128 points x CTAN outs. Warps 4x2; warp tile 32 x (CTAN/2).
// ---------------------------------------------------------------------------
template<int MODE>
__global__ __launch_bounds__(256) void mlp_gemm(
    const int* __restrict__ c0, const int* __restrict__ c1,
    const int* __restrict__ c2, const float* __restrict__ bias)
{
    constexpr int CIN  = (MODE == 1) ? 64 : 256;
    constexpr int COUT = (MODE == 3) ? 64 : 256;
    constexpr int CTAN = (COUT >= 256) ? 128 : 64;
    constexpr int NT   = CTAN / 16;
    constexpr int SB_HI = 2 * 128 * RSTR;
    constexpr int SB_LO = SB_HI + CTAN * RSTR;

    extern __shared__ char smem[];
    const int tid = threadIdx.x;
    const int warp = tid >> 5, lane = tid & 31;
    const int wm = warp >> 1, wn = warp & 1;
    const int g = lane >> 2, tg = lane & 3;
    const int p0 = blockIdx.x * 128;
    const int n0 = blockIdx.y * CTAN;

    const int m = tid >> 1, half = tid & 1;
    const int row = p0 + m;

    float acc[2][NT][4];
    #pragma unroll
    for (int mt = 0; mt < 2; mt++)
        #pragma unroll
        for (int nt = 0; nt < NT; nt++)
            #pragma unroll
            for (int q = 0; q < 4; q++) acc[mt][nt][q] = 0.f;

    for (int cb = 0; cb < CIN; cb += 64) {
        __syncthreads();
        // ---- stage A (128 rows x 64 k, hi/lo) ----
        if (MODE == 1) {
            bool ok = row < NPTS;
            const float4* src = nullptr;
            if (ok) {
                int v = c0[row] * DD + c1[row] * DIM + c2[row];
                src = (const float4*)(g_f2 + (size_t)v * 64 + half * 32);
            }
            u32 hw[16], lw[16];
            #pragma unroll
            for (int i = 0; i < 8; i++) {
                float4 q = ok ? src[i] : make_float4(0.f, 0.f, 0.f, 0.f);
                __nv_bfloat16 ah = __float2bfloat16_rn(q.x);
                __nv_bfloat16 al = __float2bfloat16_rn(q.x - __bfloat162float(ah));
                __nv_bfloat16 bh = __float2bfloat16_rn(q.y);
                __nv_bfloat16 bl = __float2bfloat16_rn(q.y - __bfloat162float(bh));
                hw[2*i]   = pkbf(ah, bh);
                lw[2*i]   = pkbf(al, bl);
                ah = __float2bfloat16_rn(q.z);
                al = __float2bfloat16_rn(q.z - __bfloat162float(ah));
                bh = __float2bfloat16_rn(q.w);
                bl = __float2bfloat16_rn(q.w - __bfloat162float(bh));
                hw[2*i+1] = pkbf(ah, bh);
                lw[2*i+1] = pkbf(al, bl);
            }
            #pragma unroll
            for (int i = 0; i < 4; i++) {
                u32 off = m * RSTR + half * 64 + i * 16;
                *(uint4*)(smem + SA_HI + off) =
                    make_uint4(hw[4*i], hw[4*i+1], hw[4*i+2], hw[4*i+3]);
                *(uint4*)(smem + SA_LO + off) =
                    make_uint4(lw[4*i], lw[4*i+1], lw[4*i+2], lw[4*i+3]);
            }
        } else {
            const __nv_bfloat16* Ahi = (MODE == 2) ? g_h1hi : g_h2hi;
            const __nv_bfloat16* Alo = (MODE == 2) ? g_h1lo : g_h2lo;
            const uint4* shi = (const uint4*)(Ahi + (size_t)row * CIN + cb + half * 32);
            const uint4* slo = (const uint4*)(Alo + (size_t)row * CIN + cb + half * 32);
            #pragma unroll
            for (int i = 0; i < 4; i++) {
                u32 off = m * RSTR + half * 64 + i * 16;
                *(uint4*)(smem + SA_HI + off) = shi[i];
                *(uint4*)(smem + SA_LO + off) = slo[i];
            }
        }
        // ---- stage B (CTAN rows x 64 k, hi/lo) ----
        {
            const __nv_bfloat16* Whi =
                (MODE == 1) ? g_mw1hi : (MODE == 2) ? g_mw2hi : g_mw3hi;
            const __nv_bfloat16* Wlo =
                (MODE == 1) ? g_mw1lo : (MODE == 2) ? g_mw2lo : g_mw3lo;
            for (int u = tid; u < CTAN * 2; u += 256) {
                int n = u >> 1, h = u & 1;
                const uint4* sh =
                    (const uint4*)(Whi + (size_t)(n0 + n) * CIN + cb + h * 32);
                const uint4* sl =
                    (const uint4*)(Wlo + (size_t)(n0 + n) * CIN + cb + h * 32);
                #pragma unroll
                for (int i = 0; i < 4; i++) {
                    u32 off = n * RSTR + h * 64 + i * 16;
                    *(uint4*)(smem + SB_HI + off) = sh[i];
                    *(uint4*)(smem + SB_LO + off) = sl[i];
                }
            }
        }
        __syncthreads();

        #pragma unroll
        for (int ks = 0; ks < 4; ks++) {
            u32 ah[2][4], al[2][4];
            #pragma unroll
            for (int mt = 0; mt < 2; mt++) {
                u32 base = (wm * 32 + mt * 16 + g) * RSTR + ks * 32 + tg * 4;
                ah[mt][0] = *(const u32*)(smem + SA_HI + base);
                ah[mt][1] = *(const u32*)(smem + SA_HI + base + 8 * RSTR);
                ah[mt][2] = *(const u32*)(smem + SA_HI + base + 16);
                ah[mt][3] = *(const u32*)(smem + SA_HI + base + 8 * RSTR + 16);
                al[mt][0] = *(const u32*)(smem + SA_LO + base);
                al[mt][1] = *(const u32*)(smem + SA_LO + base + 8 * RSTR);
                al[mt][2] = *(const u32*)(smem + SA_LO + base + 16);
                al[mt][3] = *(const u32*)(smem + SA_LO + base + 8 * RSTR + 16);
            }
            u32 bh[NT][2], bl[NT][2];
            #pragma unroll
            for (int nt = 0; nt < NT; nt++) {
                u32 base = (wn * (CTAN / 2) + nt * 8 + g) * RSTR + ks * 32 + tg * 4;
                bh[nt][0] = *(const u32*)(smem + SB_HI + base);
                bh[nt][1] = *(const u32*)(smem + SB_HI + base + 16);
                bl[nt][0] = *(const u32*)(smem + SB_LO + base);
                bl[nt][1] = *(const u32*)(smem + SB_LO + base + 16);
            }
            #pragma unroll
            for (int mt = 0; mt < 2; mt++)
                #pragma unroll
                for (int nt = 0; nt < NT; nt++) {
                    mma16816(acc[mt][nt], ah[mt], bh[nt]);
                    mma16816(acc[mt][nt], ah[mt], bl[nt]);
                    mma16816(acc[mt][nt], al[mt], bh[nt]);
                }
        }
    }

    // ---- epilogue ----
    #pragma unroll
    for (int mt = 0; mt < 2; mt++) {
        #pragma unroll
        for (int nt = 0; nt < NT; nt++) {
            const int nl = wn * (CTAN / 2) + nt * 8 + tg * 2;
            const int gc = n0 + nl;
            const float b0 = __ldg(bias + gc), b1 = __ldg(bias + gc + 1);
            const int pixA = p0 + wm * 32 + mt * 16 + g;
            const int pixB = pixA + 8;
            float v0 = acc[mt][nt][0] + b0;
            float v1 = acc[mt][nt][1] + b1;
            float v2 = acc[mt][nt][2] + b0;
            float v3 = acc[mt][nt][3] + b1;
            if (MODE != 3) {
                v0 = fmaxf(v0, 0.f); v1 = fmaxf(v1, 0.f);
                v2 = fmaxf(v2, 0.f); v3 = fmaxf(v3, 0.f);
                __nv_bfloat16* Ohi = (MODE == 1) ? g_h1hi : g_h2hi;
                __nv_bfloat16* Olo = (MODE == 1) ? g_h1lo : g_h2lo;
                __nv_bfloat16 h0 = __float2bfloat16_rn(v0);
                __nv_bfloat16 h1 = __float2bfloat16_rn(v1);
                __nv_bfloat16 h2 = __float2bfloat16_rn(v2);
                __nv_bfloat16 h3 = __float2bfloat16_rn(v3);
                *(u32*)(Ohi + (size_t)pixA * 256 + gc) = pkbf(h0, h1);
                *(u32*)(Ohi + (size_t)pixB * 256 + gc) = pkbf(h2, h3);
                *(u32*)(Olo + (size_t)pixA * 256 + gc) =
                    pkbf(__float2bfloat16_rn(v0 - __bfloat162float(h0)),
                         __float2bfloat16_rn(v1 - __bfloat162float(h1)));
                *(u32*)(Olo + (size_t)pixB * 256 + gc) =
                    pkbf(__float2bfloat16_rn(v2 - __bfloat162float(h2)),
                         __float2bfloat16_rn(v3 - __bfloat162float(h3)));
            } else {
                *(float2*)(g_h3 + (size_t)pixA * 64 + gc) = make_float2(v0, v1);
                *(float2*)(g_h3 + (size_t)pixB * 64 + gc) = make_float2(v2, v3);
            }
        }
    }
}

// ---------------------------------------------------------------------------
// Final layer: out[o][p] = b4[o] + sum_c w4[o][c] * h3[p][c]   (fp32)
// FIX vs R8: grid-stride the weight staging (384 > 256 threads).
// ---------------------------------------------------------------------------
__global__ __launch_bounds__(256) void mlp_l4(
    const float* __restrict__ w4, const float* __restrict__ b4,
    float* __restrict__ out)
{
    __shared__ float ws[384];
    __shared__ float bs[6];
    int tid = threadIdx.x;
    for (int i = tid; i < 384; i += 256) ws[i] = w4[i];   // <-- the fix
    if (tid < 6) bs[tid] = b4[tid];
    __syncthreads();
    int p = blockIdx.x * 256 + tid;
    if (p >= NPTS) return;
    float h[64];
    const float4* src = (const float4*)(g_h3 + (size_t)p * 64);
    #pragma unroll
    for (int i = 0; i < 16; i++) {
        float4 q = src[i];
        h[4*i] = q.x; h[4*i+1] = q.y; h[4*i+2] = q.z; h[4*i+3] = q.w;
    }
    #pragma unroll
    for (int o = 0; o < 6; o++) {
        float a = bs[o];
        #pragma unroll
        for (int c = 0; c < 64; c++)
            a = fmaf(ws[o * 64 + c], h[c], a);
        out[(size_t)o * NPTS + p] = a;
    }
}

// ---------------------------------------------------------------------------
extern "C" void kernel_launch(void* const* d_in, const int* in_sizes, int n_in,
                              void* d_out, int out_size)
{
    const float* img = (const float*)d_in[0];
    const int*   c0  = (const int*)d_in[1];
    const int*   c1  = (const int*)d_in[2];
    const int*   c2  = (const int*)d_in[3];
    const float* we1 = (const float*)d_in[4];
    const float* be1 = (const float*)d_in[5];
    const float* we2 = (const float*)d_in[6];
    const float* be2 = (const float*)d_in[7];
    const float* wp1 = (const float*)d_in[8];
    const float* bp1 = (const float*)d_in[9];
    const float* wp2 = (const float*)d_in[10];
    const float* bp2 = (const float*)d_in[11];
    const float* wp3 = (const float*)d_in[12];
    const float* bp3 = (const float*)d_in[13];
    const float* wp4 = (const float*)d_in[14];
    const float* bp4 = (const float*)d_in[15];
    float* out = (float*)d_out;

    cudaFuncSetAttribute(conv_mma<1>,
                         cudaFuncAttributeMaxDynamicSharedMemorySize, SMEM_CONV);
    cudaFuncSetAttribute(conv_mma<2>,
                         cudaFuncAttributeMaxDynamicSharedMemorySize, SMEM_CONV);
    const int smemG1 = 2 * 128 * RSTR + 2 * 128 * RSTR;   // 73728
    const int smemG3 = 2 * 128 * RSTR + 2 * 64 * RSTR;    // 55296
    cudaFuncSetAttribute(mlp_gemm<1>,
                         cudaFuncAttributeMaxDynamicSharedMemorySize, smemG1);
    cudaFuncSetAttribute(mlp_gemm<2>,
                         cudaFuncAttributeMaxDynamicSharedMemorySize, smemG1);
    cudaFuncSetAttribute(mlp_gemm<3>,
                         cudaFuncAttributeMaxDynamicSharedMemorySize, smemG3);

    __nv_bfloat16 *mw1hi, *mw1lo, *mw2hi, *mw2lo, *mw3hi, *mw3lo;
    cudaGetSymbolAddress((void**)&mw1hi, g_mw1hi);
    cudaGetSymbolAddress((void**)&mw1lo, g_mw1lo);
    cudaGetSymbolAddress((void**)&mw2hi, g_mw2hi);
    cudaGetSymbolAddress((void**)&mw2lo, g_mw2lo);
    cudaGetSymbolAddress((void**)&mw3hi, g_mw3hi);
    cudaGetSymbolAddress((void**)&mw3lo, g_mw3lo);

    prep_img<<<2000, 256>>>(img);
    prep_w1<<<(14 * 4096 + 255) / 256, 256>>>(we1);
    prep_w2<<<(27 * 4096 + 255) / 256, 256>>>(we2);
    prep_wmlp<<<(256 * 64 + 255) / 256, 256>>>(wp1, mw1hi, mw1lo, 256 * 64);
    prep_wmlp<<<(256 * 256 + 255) / 256, 256>>>(wp2, mw2hi, mw2lo, 256 * 256);
    prep_wmlp<<<(64 * 256 + 255) / 256, 256>>>(wp3, mw3hi, mw3lo, 64 * 256);

    conv_mma<1><<<4000, 256, SMEM_CONV>>>(be1);
    conv_mma<2><<<4000, 256, SMEM_CONV>>>(be2);

    dim3 g12(NPAD / 128, 2);
    mlp_gemm<1><<<g12, 256, smemG1>>>(c0, c1, c2, bp1);
    mlp_gemm<2><<<g12, 256, smemG1>>>(c0, c1, c2, bp2);
    dim3 g3(NPAD / 128, 1);
    mlp_gemm<3><<<g3, 256, smemG3>>>(c0, c1, c2, bp3);
    mlp_l4<<<(NPTS + 255) / 256, 256>>>(wp4, bp4, out);
}